// round 3
// baseline (speedup 1.0000x reference)
#include <cuda_runtime.h>
#include <math_constants.h>

#define BB 64
#define LL 4096
#define DD 512
#define NS 16                // L-splits per batch row -> 1024 CTAs, 256 rows each
#define CHUNK (LL / NS)      // 256 rows per CTA
#define WARPS 8
#define NTHREADS (WARPS * 32)

// scratch: per (b, split): c[512] at local-max reference, then m, then s
__device__ float g_scratch[BB * NS * (DD + 2)];
__device__ int   g_cnt[BB];          // zero-init; last CTA resets -> replay-safe

__device__ __forceinline__ float ldcg(const float* p) {
    float v;
    asm volatile("ld.global.cg.f32 %0, [%1];" : "=f"(v) : "l"(p));
    return v;
}

__global__ void __launch_bounds__(NTHREADS, 2)
attn_fused(const float* __restrict__ h, const float* __restrict__ E,
           float* __restrict__ outp) {
    const int b     = blockIdx.x / NS;
    const int split = blockIdx.x % NS;
    const int tid   = threadIdx.x;
    const int wid   = tid >> 5;
    const int lane  = tid & 31;

    // h[b]: lane j holds float4 indices j + 32q
    const float4* h4 = (const float4*)(h + (size_t)b * DD);
    float4 hv[4];
#pragma unroll
    for (int q = 0; q < 4; q++) hv[q] = h4[lane + 32 * q];

    const float4* Eb  = (const float4*)(E + (size_t)b * LL * DD);
    const int row0    = split * CHUNK;

    float m = -CUDART_INF_F;
    float s = 0.f;
    float4 c[4];
#pragma unroll
    for (int q = 0; q < 4; q++) c[q] = make_float4(0.f, 0.f, 0.f, 0.f);

    // 2 rows per warp-iteration, manual double-buffer prefetch.
    // CHUNK/2 = 128 pairs, 8 warps -> 16 iterations per warp.
    const int NPAIR = CHUNK / 2;
    float4 vA[4], vB[4];
    {
        const float4* rowA = Eb + (size_t)(row0 + 2 * wid) * (DD / 4);
        const float4* rowB = rowA + (DD / 4);
#pragma unroll
        for (int q = 0; q < 4; q++) vA[q] = rowA[lane + 32 * q];
#pragma unroll
        for (int q = 0; q < 4; q++) vB[q] = rowB[lane + 32 * q];
    }

    for (int p = wid; p < NPAIR; p += WARPS) {
        // prefetch next pair while current is processed
        float4 nA[4], nB[4];
        const int pn = p + WARPS;
        if (pn < NPAIR) {
            const float4* rowA = Eb + (size_t)(row0 + 2 * pn) * (DD / 4);
            const float4* rowB = rowA + (DD / 4);
#pragma unroll
            for (int q = 0; q < 4; q++) nA[q] = rowA[lane + 32 * q];
#pragma unroll
            for (int q = 0; q < 4; q++) nB[q] = rowB[lane + 32 * q];
        }

        float d0 = 0.f, d1 = 0.f;
#pragma unroll
        for (int q = 0; q < 4; q++) {
            d0 = fmaf(vA[q].x, hv[q].x, d0);
            d1 = fmaf(vB[q].x, hv[q].x, d1);
            d0 = fmaf(vA[q].y, hv[q].y, d0);
            d1 = fmaf(vB[q].y, hv[q].y, d1);
            d0 = fmaf(vA[q].z, hv[q].z, d0);
            d1 = fmaf(vB[q].z, hv[q].z, d1);
            d0 = fmaf(vA[q].w, hv[q].w, d0);
            d1 = fmaf(vB[q].w, hv[q].w, d1);
        }
#pragma unroll
        for (int o = 16; o > 0; o >>= 1) {
            d0 += __shfl_xor_sync(0xffffffffu, d0, o);
            d1 += __shfl_xor_sync(0xffffffffu, d1, o);
        }
        const float e0 = d0, e1 = d1;
        const float emax = fmaxf(e0, e1);

        if (emax > m) {                    // warp-uniform, rarely taken
            const float sc = __expf(m - emax);
            s *= sc;
#pragma unroll
            for (int q = 0; q < 4; q++) {
                c[q].x *= sc; c[q].y *= sc; c[q].z *= sc; c[q].w *= sc;
            }
            m = emax;
        }
        const float p0 = __expf(e0 - m);
        const float p1 = __expf(e1 - m);
        s += p0 + p1;
#pragma unroll
        for (int q = 0; q < 4; q++) {
            c[q].x = fmaf(p0, vA[q].x, c[q].x);
            c[q].y = fmaf(p0, vA[q].y, c[q].y);
            c[q].z = fmaf(p0, vA[q].z, c[q].z);
            c[q].w = fmaf(p0, vA[q].w, c[q].w);
            c[q].x = fmaf(p1, vB[q].x, c[q].x);
            c[q].y = fmaf(p1, vB[q].y, c[q].y);
            c[q].z = fmaf(p1, vB[q].z, c[q].z);
            c[q].w = fmaf(p1, vB[q].w, c[q].w);
        }

#pragma unroll
        for (int q = 0; q < 4; q++) { vA[q] = nA[q]; vB[q] = nB[q]; }
    }

    // ---- combine the 8 warps within the CTA ----
    __shared__ float sm_c[WARPS][DD];
    __shared__ float sm_m[WARPS], sm_s[WARPS], sm_sc[WARPS];
    __shared__ float sm_mg, sm_stot;
    __shared__ int   sm_last;

#pragma unroll
    for (int q = 0; q < 4; q++) {
        const int d0i = 4 * lane + 128 * q;
        sm_c[wid][d0i + 0] = c[q].x;
        sm_c[wid][d0i + 1] = c[q].y;
        sm_c[wid][d0i + 2] = c[q].z;
        sm_c[wid][d0i + 3] = c[q].w;
    }
    if (lane == 0) { sm_m[wid] = m; sm_s[wid] = s; }
    __syncthreads();

    if (wid == 0) {
        float mw = (lane < WARPS) ? sm_m[lane] : -CUDART_INF_F;
        float mg = mw;
#pragma unroll
        for (int o = 16; o > 0; o >>= 1)
            mg = fmaxf(mg, __shfl_xor_sync(0xffffffffu, mg, o));
        float sc = (lane < WARPS) ? __expf(mw - mg) : 0.f;
        float st = (lane < WARPS) ? sm_s[lane] * sc : 0.f;
#pragma unroll
        for (int o = 16; o > 0; o >>= 1)
            st += __shfl_xor_sync(0xffffffffu, st, o);
        if (lane < WARPS) sm_sc[lane] = sc;
        if (lane == 0) { sm_mg = mg; sm_stot = st; }
    }
    __syncthreads();

    float* out = g_scratch + ((size_t)b * NS + split) * (DD + 2);
    for (int d = tid; d < DD; d += NTHREADS) {
        float acc = 0.f;
#pragma unroll
        for (int w = 0; w < WARPS; w++)
            acc = fmaf(sm_c[w][d], sm_sc[w], acc);
        out[d] = acc;
    }
    if (tid == 0) { out[DD] = sm_mg; out[DD + 1] = sm_stot; }

    // ---- last-CTA-per-batch combine (replaces pass2) ----
    if (tid == 0) {
        __threadfence();
        sm_last = (atomicAdd(&g_cnt[b], 1) == NS - 1);
    }
    __syncthreads();
    if (!sm_last) return;

    __shared__ float sm2_sc[NS];
    __shared__ float sm2_stot;
    const float* base = g_scratch + (size_t)b * NS * (DD + 2);

    if (tid < 32) {
        float mw = (tid < NS) ? ldcg(base + (size_t)tid * (DD + 2) + DD)
                              : -CUDART_INF_F;
        float mg = mw;
#pragma unroll
        for (int o = 16; o > 0; o >>= 1)
            mg = fmaxf(mg, __shfl_xor_sync(0xffffffffu, mg, o));
        float sc = (tid < NS) ? __expf(mw - mg) : 0.f;
        float st = (tid < NS) ? ldcg(base + (size_t)tid * (DD + 2) + DD + 1) * sc
                              : 0.f;
#pragma unroll
        for (int o = 16; o > 0; o >>= 1)
            st += __shfl_xor_sync(0xffffffffu, st, o);
        if (tid < NS) sm2_sc[tid] = sc;
        if (tid == 0) sm2_stot = st;
    }
    __syncthreads();

    const float inv = 1.f / (sm2_stot * (float)LL);
#pragma unroll
    for (int dd = 0; dd < DD / NTHREADS; dd++) {
        const int d = tid + dd * NTHREADS;
        float acc = 0.f;
#pragma unroll
        for (int w = 0; w < NS; w++)
            acc = fmaf(ldcg(base + (size_t)w * (DD + 2) + d), sm2_sc[w], acc);
        outp[(size_t)b * DD + d] = acc * inv;
    }

    if (tid == 0) g_cnt[b] = 0;   // reset for next graph replay
}

extern "C" void kernel_launch(void* const* d_in, const int* in_sizes, int n_in,
                              void* d_out, int out_size) {
    const float* h = (const float*)d_in[0];   // current_hidden [64, 512]
    const float* E = (const float*)d_in[1];   // encoder_outputs [64, 4096, 512]
    float* outp = (float*)d_out;              // [64, 512]

    attn_fused<<<BB * NS, NTHREADS>>>(h, E, outp);
}

// round 4
// speedup vs baseline: 1.0116x; 1.0116x over previous
#include <cuda_runtime.h>
#include <math_constants.h>

#define BB 64
#define LL 4096
#define DD 512
#define WARPS 8
#define NTHREADS 256
#define GRID 296                       // 2 CTAs per SM on 148 SMs
#define PAIRS_PER_B (LL / 2)           // 2048
#define TOTAL_PAIRS (BB * PAIRS_PER_B) // 131072
#define PBASE (TOTAL_PAIRS / GRID)     // 442
#define PREM  (TOTAL_PAIRS % GRID)     // 240
#define MAXSLOT 8                      // <=6 CTAs can overlap one b

// per (b, slot): c[512] at CTA-local max reference, then m, then s
__device__ float g_scratch[BB * MAXSLOT * (DD + 2)];
__device__ int   g_slotc[BB];   // slot allocator (combiner resets)
__device__ int   g_done[BB];    // pairs-done counter (combiner resets)

static __device__ __forceinline__ float ldcg(const float* p) {
    float v;
    asm volatile("ld.global.cg.f32 %0, [%1];" : "=f"(v) : "l"(p));
    return v;
}

__global__ void __launch_bounds__(NTHREADS, 2)
attn_ws(const float* __restrict__ h, const float* __restrict__ E,
        float* __restrict__ outp) {
    const int tid  = threadIdx.x;
    const int wid  = tid >> 5;
    const int lane = tid & 31;
    const int cta  = blockIdx.x;

    const int pstart = cta * PBASE + min(cta, PREM);
    const int pcount = PBASE + (cta < PREM ? 1 : 0);
    const int pend   = pstart + pcount;

    __shared__ float sm_c[WARPS][DD];
    __shared__ float sm_m[WARPS], sm_s[WARPS], sm_sc[WARPS];
    __shared__ float sm_cmb_sc[MAXSLOT];
    __shared__ float sm_stot;
    __shared__ int   sm_slot, sm_docmb, sm_nslot;

    int ps = pstart;
    while (ps < pend) {                       // <= 2 segments per CTA
        const int b    = ps / PAIRS_PER_B;
        const int pe   = min(pend, (b + 1) * PAIRS_PER_B);
        const int nseg = pe - ps;

        // h[b]: lane j holds float4 indices j + 32q
        const float4* h4 = (const float4*)(h + (size_t)b * DD);
        float4 hv[4];
#pragma unroll
        for (int q = 0; q < 4; q++) hv[q] = h4[lane + 32 * q];

        float m = -CUDART_INF_F;
        float s = 0.f;
        float4 c[4];
#pragma unroll
        for (int q = 0; q < 4; q++) c[q] = make_float4(0.f, 0.f, 0.f, 0.f);

        // two rows (one pair) per warp-iteration; rows are globally contiguous
        for (int lp = wid; lp < nseg; lp += WARPS) {
            const float4* rowA = (const float4*)(E + (size_t)(ps + lp) * 2 * DD);
            const float4* rowB = rowA + (DD / 4);
            float4 vA[4], vB[4];
#pragma unroll
            for (int q = 0; q < 4; q++) vA[q] = rowA[lane + 32 * q];
#pragma unroll
            for (int q = 0; q < 4; q++) vB[q] = rowB[lane + 32 * q];

            float d0 = 0.f, d1 = 0.f;
#pragma unroll
            for (int q = 0; q < 4; q++) {
                d0 = fmaf(vA[q].x, hv[q].x, d0);
                d1 = fmaf(vB[q].x, hv[q].x, d1);
                d0 = fmaf(vA[q].y, hv[q].y, d0);
                d1 = fmaf(vB[q].y, hv[q].y, d1);
                d0 = fmaf(vA[q].z, hv[q].z, d0);
                d1 = fmaf(vB[q].z, hv[q].z, d1);
                d0 = fmaf(vA[q].w, hv[q].w, d0);
                d1 = fmaf(vB[q].w, hv[q].w, d1);
            }
#pragma unroll
            for (int o = 16; o > 0; o >>= 1) {
                d0 += __shfl_xor_sync(0xffffffffu, d0, o);
                d1 += __shfl_xor_sync(0xffffffffu, d1, o);
            }
            const float e0 = d0, e1 = d1;
            const float emax = fmaxf(e0, e1);

            if (emax > m) {                   // warp-uniform, rarely taken
                const float sc = __expf(m - emax);
                s *= sc;
#pragma unroll
                for (int q = 0; q < 4; q++) {
                    c[q].x *= sc; c[q].y *= sc; c[q].z *= sc; c[q].w *= sc;
                }
                m = emax;
            }
            const float p0 = __expf(e0 - m);
            const float p1 = __expf(e1 - m);
            s += p0 + p1;
#pragma unroll
            for (int q = 0; q < 4; q++) {
                c[q].x = fmaf(p0, vA[q].x, c[q].x);
                c[q].y = fmaf(p0, vA[q].y, c[q].y);
                c[q].z = fmaf(p0, vA[q].z, c[q].z);
                c[q].w = fmaf(p0, vA[q].w, c[q].w);
                c[q].x = fmaf(p1, vB[q].x, c[q].x);
                c[q].y = fmaf(p1, vB[q].y, c[q].y);
                c[q].z = fmaf(p1, vB[q].z, c[q].z);
                c[q].w = fmaf(p1, vB[q].w, c[q].w);
            }
        }

        // ---- CTA combine of the 8 warps ----
        __syncthreads();                      // smem reuse guard
#pragma unroll
        for (int q = 0; q < 4; q++) {
            const int d0i = 4 * lane + 128 * q;
            sm_c[wid][d0i + 0] = c[q].x;
            sm_c[wid][d0i + 1] = c[q].y;
            sm_c[wid][d0i + 2] = c[q].z;
            sm_c[wid][d0i + 3] = c[q].w;
        }
        if (lane == 0) { sm_m[wid] = m; sm_s[wid] = s; }
        if (tid == 0) sm_slot = atomicAdd(&g_slotc[b], 1);
        __syncthreads();

        if (wid == 0) {
            float mw = (lane < WARPS) ? sm_m[lane] : -CUDART_INF_F;
            float mg = mw;
#pragma unroll
            for (int o = 16; o > 0; o >>= 1)
                mg = fmaxf(mg, __shfl_xor_sync(0xffffffffu, mg, o));
            float sc = (lane < WARPS) ? __expf(mw - mg) : 0.f;
            float st = (lane < WARPS) ? sm_s[lane] * sc : 0.f;
#pragma unroll
            for (int o = 16; o > 0; o >>= 1)
                st += __shfl_xor_sync(0xffffffffu, st, o);
            if (lane < WARPS) sm_sc[lane] = sc;
            if (lane == 0) { sm_m[0] = mg; sm_s[0] = st; }   // reuse slots 0
        }
        __syncthreads();

        // ---- flush partial (c @ mg reference, mg, st) to scratch slot ----
        float* out = g_scratch + ((size_t)b * MAXSLOT + sm_slot) * (DD + 2);
#pragma unroll
        for (int dd = 0; dd < DD / NTHREADS; dd++) {
            const int d = tid + dd * NTHREADS;
            float acc = 0.f;
#pragma unroll
            for (int w = 0; w < WARPS; w++)
                acc = fmaf(sm_c[w][d], sm_sc[w], acc);
            out[d] = acc;
        }
        if (tid == 0) { out[DD] = sm_m[0]; out[DD + 1] = sm_s[0]; }

        __threadfence();
        if (tid == 0) {
            const int old = atomicAdd(&g_done[b], nseg);
            sm_docmb = (old + nseg == PAIRS_PER_B);
            if (sm_docmb) sm_nslot = atomicAdd(&g_slotc[b], 0);
        }
        __syncthreads();

        // ---- last CTA for this b: combine slots, write output ----
        if (sm_docmb) {
            const int nslot = sm_nslot;
            const float* base = g_scratch + (size_t)b * MAXSLOT * (DD + 2);
            if (tid == 0) {                  // nslot <= 6: serial is fine
                float mg = -CUDART_INF_F;
                for (int i = 0; i < nslot; i++)
                    mg = fmaxf(mg, ldcg(base + (size_t)i * (DD + 2) + DD));
                float st = 0.f;
                for (int i = 0; i < nslot; i++) {
                    const float sc = __expf(ldcg(base + (size_t)i * (DD + 2) + DD) - mg);
                    sm_cmb_sc[i] = sc;
                    st = fmaf(sc, ldcg(base + (size_t)i * (DD + 2) + DD + 1), st);
                }
                sm_stot = st;
            }
            __syncthreads();

            const float inv = 1.f / (sm_stot * (float)LL);
#pragma unroll
            for (int dd = 0; dd < DD / NTHREADS; dd++) {
                const int d = tid + dd * NTHREADS;
                float acc = 0.f;
                for (int i = 0; i < nslot; i++)
                    acc = fmaf(ldcg(base + (size_t)i * (DD + 2) + d),
                               sm_cmb_sc[i], acc);
                outp[(size_t)b * DD + d] = acc * inv;
            }
            if (tid == 0) {                  // reset for next graph replay
                g_slotc[b] = 0;
                g_done[b]  = 0;
            }
        }
        __syncthreads();
        ps = pe;
    }
}

extern "C" void kernel_launch(void* const* d_in, const int* in_sizes, int n_in,
                              void* d_out, int out_size) {
    const float* h = (const float*)d_in[0];   // current_hidden [64, 512]
    const float* E = (const float*)d_in[1];   // encoder_outputs [64, 4096, 512]
    float* outp = (float*)d_out;              // [64, 512]

    attn_ws<<<GRID, NTHREADS>>>(h, E, outp);
}

// round 5
// speedup vs baseline: 1.0200x; 1.0084x over previous
#include <cuda_runtime.h>
#include <math_constants.h>
#include <cstdint>

#define BB 64
#define LL 4096
#define DD 512
#define ROWB (DD * 4)                   // 2048 bytes per row
#define SROWS 8                         // rows per stage (1 per consumer warp)
#define STAGE_BYTES (SROWS * ROWB)      // 16384
#define STAGES 4
#define SPB (LL / SROWS)                // 512 stages per batch
#define TOTAL_STAGES (BB * SPB)         // 32768
#define GRID 296                        // 2 CTAs/SM on 148 SMs
#define PBASE (TOTAL_STAGES / GRID)     // 110
#define PREM  (TOTAL_STAGES % GRID)     // 208
#define CWARPS 8
#define NTHREADS (CWARPS * 32 + 32)     // 8 consumer warps + 1 producer warp
#define MAXSLOT 8

// dynamic smem: [0,64): full[4]+empty[4] mbarriers; [1024, 1024+4*16384): tiles
#define MBAR_OFF 0
#define TILE_OFF 1024
#define DYN_SMEM (TILE_OFF + STAGES * STAGE_BYTES)

// per (b, slot): c[512] at slot-local max reference, then m, then s
__device__ float g_scratch[BB * MAXSLOT * (DD + 2)];
__device__ int   g_done[BB];            // combiner resets -> graph-replay safe

static __device__ __forceinline__ uint32_t smem_u32(const void* p) {
    uint32_t a;
    asm("{ .reg .u64 t; cvta.to.shared.u64 t, %1; cvt.u32.u64 %0, t; }"
        : "=r"(a) : "l"(p));
    return a;
}
static __device__ __forceinline__ void mbar_init(uint32_t m, uint32_t cnt) {
    asm volatile("mbarrier.init.shared.b64 [%0], %1;" :: "r"(m), "r"(cnt) : "memory");
}
static __device__ __forceinline__ void mbar_wait_acq(uint32_t m, uint32_t par) {
    asm volatile(
        "{\n\t.reg .pred P;\n\t"
        "W%=:\n\t"
        "mbarrier.try_wait.parity.acquire.cta.shared::cta.b64 P, [%0], %1, 0x989680;\n\t"
        "@!P bra W%=;\n\t}"
        :: "r"(m), "r"(par) : "memory");
}
static __device__ __forceinline__ void mbar_wait_rlx(uint32_t m, uint32_t par) {
    asm volatile(
        "{\n\t.reg .pred P;\n\t"
        "W%=:\n\t"
        "mbarrier.try_wait.parity.relaxed.cta.shared::cta.b64 P, [%0], %1, 0x989680;\n\t"
        "@!P bra W%=;\n\t}"
        :: "r"(m), "r"(par) : "memory");
}
static __device__ __forceinline__ void mbar_arrive(uint32_t m) {
    asm volatile("mbarrier.arrive.shared.b64 _, [%0];" :: "r"(m) : "memory");
}
static __device__ __forceinline__ void mbar_expect_tx(uint32_t m, uint32_t bytes) {
    asm volatile("mbarrier.arrive.expect_tx.shared.b64 _, [%0], %1;"
                 :: "r"(m), "r"(bytes) : "memory");
}
static __device__ __forceinline__ void bulk_g2s(uint32_t dst, const void* src,
                                                uint32_t bytes, uint32_t mbar) {
    asm volatile(
        "cp.async.bulk.shared::cta.global.mbarrier::complete_tx::bytes [%0], [%1], %2, [%3];"
        :: "r"(dst), "l"(src), "r"(bytes), "r"(mbar) : "memory");
}
static __device__ __forceinline__ float ldcg(const float* p) {
    float v;
    asm volatile("ld.global.cg.f32 %0, [%1];" : "=f"(v) : "l"(p));
    return v;
}
// which CTA owns global stage s (inverse of the PBASE/PREM partition)
static __device__ __forceinline__ int ctaof(int s) {
    const int cut = PREM * (PBASE + 1);         // 208*111 = 23088
    return (s < cut) ? s / (PBASE + 1) : PREM + (s - cut) / PBASE;
}
#define CBAR() asm volatile("bar.sync 1, %0;" :: "n"(CWARPS * 32) : "memory")

__global__ void __launch_bounds__(NTHREADS, 2)
attn_tma(const float* __restrict__ h, const float* __restrict__ E,
         float* __restrict__ outp) {
    extern __shared__ char dsm[];
    const uint32_t smb   = smem_u32(dsm);
    const int tid  = threadIdx.x;
    const int wid  = tid >> 5;
    const int lane = tid & 31;
    const int cta  = blockIdx.x;

    const int pstart = cta * PBASE + min(cta, PREM);
    const int pend   = pstart + PBASE + (cta < PREM ? 1 : 0);

    if (tid == 0) {
#pragma unroll
        for (int i = 0; i < STAGES; i++) {
            mbar_init(smb + MBAR_OFF + i * 8, 1);                // full: 1 tx-arrive
            mbar_init(smb + MBAR_OFF + 32 + i * 8, CWARPS);      // empty: 8 warps
        }
    }
    __syncthreads();

    // ================= producer warp =================
    if (wid == CWARPS) {
        if (lane == 0) {
            uint32_t buf = 0, ph = 1;
            for (int st = pstart; st < pend; ++st) {
                mbar_wait_rlx(smb + MBAR_OFF + 32 + buf * 8, ph);
                mbar_expect_tx(smb + MBAR_OFF + buf * 8, STAGE_BYTES);
                bulk_g2s(smb + TILE_OFF + buf * STAGE_BYTES,
                         (const char*)E + (size_t)st * STAGE_BYTES,
                         STAGE_BYTES, smb + MBAR_OFF + buf * 8);
                if (++buf == STAGES) { buf = 0; ph ^= 1; }
            }
        }
        return;   // producer warp exits; consumers use named barrier only
    }

    // ================= consumer warps (tid 0..255) =================
    __shared__ float sm_c[CWARPS][DD];
    __shared__ float sm_m[CWARPS], sm_s[CWARPS], sm_sc[CWARPS];
    __shared__ float sm_cmb_sc[MAXSLOT];
    __shared__ float sm_stot;
    __shared__ int   sm_docmb;

    uint32_t buf = 0, ph = 0;
    int ps = pstart;
    while (ps < pend) {                        // <= 2 segments
        const int b  = ps / SPB;
        const int se = min(pend, (b + 1) * SPB);

        const float4* h4 = (const float4*)(h + (size_t)b * DD);
        float4 hv[4];
#pragma unroll
        for (int q = 0; q < 4; q++) hv[q] = h4[lane + 32 * q];

        float m = -CUDART_INF_F;
        float s = 0.f;
        float4 c[4];
#pragma unroll
        for (int q = 0; q < 4; q++) c[q] = make_float4(0.f, 0.f, 0.f, 0.f);

        for (int st = ps; st < se; ++st) {
            mbar_wait_acq(smb + MBAR_OFF + buf * 8, ph);

            const float4* row = (const float4*)(dsm + TILE_OFF +
                                                buf * STAGE_BYTES + wid * ROWB);
            float4 v[4];
#pragma unroll
            for (int q = 0; q < 4; q++) v[q] = row[lane + 32 * q];

            float da = 0.f, db = 0.f;                 // 2 chains halve FMA latency
#pragma unroll
            for (int q = 0; q < 4; q++) {
                da = fmaf(v[q].x, hv[q].x, da);
                db = fmaf(v[q].y, hv[q].y, db);
                da = fmaf(v[q].z, hv[q].z, da);
                db = fmaf(v[q].w, hv[q].w, db);
            }
            float d0 = da + db;
#pragma unroll
            for (int o = 16; o > 0; o >>= 1)
                d0 += __shfl_xor_sync(0xffffffffu, d0, o);
            const float e = d0;

            if (e > m) {                              // warp-uniform, rare
                const float sc = __expf(m - e);
                s *= sc;
#pragma unroll
                for (int q = 0; q < 4; q++) {
                    c[q].x *= sc; c[q].y *= sc; c[q].z *= sc; c[q].w *= sc;
                }
                m = e;
            }
            const float p = __expf(e - m);
            s += p;
#pragma unroll
            for (int q = 0; q < 4; q++) {
                c[q].x = fmaf(p, v[q].x, c[q].x);
                c[q].y = fmaf(p, v[q].y, c[q].y);
                c[q].z = fmaf(p, v[q].z, c[q].z);
                c[q].w = fmaf(p, v[q].w, c[q].w);
            }
            __syncwarp();
            if (lane == 0) mbar_arrive(smb + MBAR_OFF + 32 + buf * 8);
            if (++buf == STAGES) { buf = 0; ph ^= 1; }
        }

        // ---- combine 8 warps (consumer-only named barrier) ----
        CBAR();                                       // guard sm_* reuse
#pragma unroll
        for (int q = 0; q < 4; q++) {
            const int d0i = 4 * lane + 128 * q;
            sm_c[wid][d0i + 0] = c[q].x;
            sm_c[wid][d0i + 1] = c[q].y;
            sm_c[wid][d0i + 2] = c[q].z;
            sm_c[wid][d0i + 3] = c[q].w;
        }
        if (lane == 0) { sm_m[wid] = m; sm_s[wid] = s; }
        CBAR();

        if (wid == 0) {
            float mw = (lane < CWARPS) ? sm_m[lane] : -CUDART_INF_F;
            float mg = mw;
#pragma unroll
            for (int o = 16; o > 0; o >>= 1)
                mg = fmaxf(mg, __shfl_xor_sync(0xffffffffu, mg, o));
            float sc = (lane < CWARPS) ? __expf(mw - mg) : 0.f;
            float st = (lane < CWARPS) ? sm_s[lane] * sc : 0.f;
#pragma unroll
            for (int o = 16; o > 0; o >>= 1)
                st += __shfl_xor_sync(0xffffffffu, st, o);
            if (lane < CWARPS) sm_sc[lane] = sc;
            if (lane == 0) { sm_m[0] = mg; sm_s[0] = st; }
        }
        CBAR();

        // deterministic slot = cta - first CTA covering b
        const int first = ctaof(b * SPB);
        const int slot  = cta - first;
        float* out = g_scratch + ((size_t)b * MAXSLOT + slot) * (DD + 2);
#pragma unroll
        for (int dd = 0; dd < 2; dd++) {
            const int d = tid + dd * 256;
            float acc = 0.f;
#pragma unroll
            for (int w = 0; w < CWARPS; w++)
                acc = fmaf(sm_c[w][d], sm_sc[w], acc);
            out[d] = acc;
        }
        if (tid == 0) { out[DD] = sm_m[0]; out[DD + 1] = sm_s[0]; }

        __threadfence();
        if (tid == 0) {
            const int old = atomicAdd(&g_done[b], se - ps);
            sm_docmb = (old + (se - ps) == SPB);
        }
        CBAR();

        if (sm_docmb) {     // last CTA for b: fixed-order combine -> deterministic
            const int nslot = ctaof(b * SPB + SPB - 1) - first + 1;
            const float* base = g_scratch + (size_t)b * MAXSLOT * (DD + 2);
            if (tid == 0) {
                float mg = -CUDART_INF_F;
                for (int i = 0; i < nslot; i++)
                    mg = fmaxf(mg, ldcg(base + (size_t)i * (DD + 2) + DD));
                float st = 0.f;
                for (int i = 0; i < nslot; i++) {
                    const float sc =
                        __expf(ldcg(base + (size_t)i * (DD + 2) + DD) - mg);
                    sm_cmb_sc[i] = sc;
                    st = fmaf(sc, ldcg(base + (size_t)i * (DD + 2) + DD + 1), st);
                }
                sm_stot = st;
            }
            CBAR();
            const float inv = 1.f / (sm_stot * (float)LL);
#pragma unroll
            for (int dd = 0; dd < 2; dd++) {
                const int d = tid + dd * 256;
                float acc = 0.f;
                for (int i = 0; i < nslot; i++)
                    acc = fmaf(ldcg(base + (size_t)i * (DD + 2) + d),
                               sm_cmb_sc[i], acc);
                outp[(size_t)b * DD + d] = acc * inv;
            }
            if (tid == 0) g_done[b] = 0;   // reset for next graph replay
        }
        CBAR();
        ps = se;
    }
}

extern "C" void kernel_launch(void* const* d_in, const int* in_sizes, int n_in,
                              void* d_out, int out_size) {
    const float* h = (const float*)d_in[0];   // current_hidden [64, 512]
    const float* E = (const float*)d_in[1];   // encoder_outputs [64, 4096, 512]
    float* outp = (float*)d_out;              // [64, 512]

    cudaFuncSetAttribute(attn_tma, cudaFuncAttributeMaxDynamicSharedMemorySize,
                         DYN_SMEM);
    attn_tma<<<GRID, NTHREADS, DYN_SMEM>>>(h, E, outp);
}

// round 6
// speedup vs baseline: 1.0409x; 1.0204x over previous
#include <cuda_runtime.h>
#include <math_constants.h>

#define BB 64
#define LL 4096
#define DD 512
#define NS 4                 // L-splits per batch row -> grid 256
#define CHUNK (LL / NS)      // 1024 rows per CTA
#define NPAIR (CHUNK / 2)    // 512 pairs (compile-time -> ptxas pipelines)
#define WARPS 8
#define NTHREADS (WARPS * 32)

// scratch: per (b, split): c[512] at local-max reference, then m, then s
__device__ float g_scratch[BB * NS * (DD + 2)];

__global__ void __launch_bounds__(NTHREADS, 2)
attn_pass1(const float* __restrict__ h, const float* __restrict__ E) {
    const int b     = blockIdx.x / NS;
    const int split = blockIdx.x % NS;
    const int tid   = threadIdx.x;
    const int wid   = tid >> 5;
    const int lane  = tid & 31;

    // load h[b] (512 floats): lane j holds float4 indices j + 32q
    const float4* h4 = (const float4*)(h + (size_t)b * DD);
    float4 hv[4];
#pragma unroll
    for (int q = 0; q < 4; q++) hv[q] = __ldg(h4 + lane + 32 * q);

    const float4* Eb  = (const float4*)(E + (size_t)b * LL * DD);
    const int row0    = split * CHUNK;

    float m = -CUDART_INF_F;
    float s = 0.f;
    float4 c[4];
#pragma unroll
    for (int q = 0; q < 4; q++) c[q] = make_float4(0.f, 0.f, 0.f, 0.f);

    // two rows per warp-iteration; static trip count lets ptxas pipeline
    for (int p = wid; p < NPAIR; p += WARPS) {
        const float4* rowA = Eb + (size_t)(row0 + 2 * p) * (DD / 4);
        const float4* rowB = rowA + (DD / 4);
        float4 vA[4], vB[4];
#pragma unroll
        for (int q = 0; q < 4; q++) vA[q] = __ldg(rowA + lane + 32 * q);
#pragma unroll
        for (int q = 0; q < 4; q++) vB[q] = __ldg(rowB + lane + 32 * q);

        float d0 = 0.f, d1 = 0.f;
#pragma unroll
        for (int q = 0; q < 4; q++) {
            d0 = fmaf(vA[q].x, hv[q].x, d0);
            d1 = fmaf(vB[q].x, hv[q].x, d1);
            d0 = fmaf(vA[q].y, hv[q].y, d0);
            d1 = fmaf(vB[q].y, hv[q].y, d1);
            d0 = fmaf(vA[q].z, hv[q].z, d0);
            d1 = fmaf(vB[q].z, hv[q].z, d1);
            d0 = fmaf(vA[q].w, hv[q].w, d0);
            d1 = fmaf(vB[q].w, hv[q].w, d1);
        }
        // interleaved warp reductions (two independent chains)
#pragma unroll
        for (int o = 16; o > 0; o >>= 1) {
            d0 += __shfl_xor_sync(0xffffffffu, d0, o);
            d1 += __shfl_xor_sync(0xffffffffu, d1, o);
        }
        const float e0 = d0, e1 = d1;
        const float emax = fmaxf(e0, e1);

        if (emax > m) {                    // warp-uniform, rarely taken
            const float sc = __expf(m - emax);
            s *= sc;
#pragma unroll
            for (int q = 0; q < 4; q++) {
                c[q].x *= sc; c[q].y *= sc; c[q].z *= sc; c[q].w *= sc;
            }
            m = emax;
        }
        const float p0 = __expf(e0 - m);
        const float p1 = __expf(e1 - m);
        s += p0 + p1;
#pragma unroll
        for (int q = 0; q < 4; q++) {
            c[q].x = fmaf(p0, vA[q].x, c[q].x);
            c[q].y = fmaf(p0, vA[q].y, c[q].y);
            c[q].z = fmaf(p0, vA[q].z, c[q].z);
            c[q].w = fmaf(p0, vA[q].w, c[q].w);
            c[q].x = fmaf(p1, vB[q].x, c[q].x);
            c[q].y = fmaf(p1, vB[q].y, c[q].y);
            c[q].z = fmaf(p1, vB[q].z, c[q].z);
            c[q].w = fmaf(p1, vB[q].w, c[q].w);
        }
    }

    // ---- combine the 8 warps within the CTA ----
    __shared__ float sm_c[WARPS][DD];
    __shared__ float sm_m[WARPS], sm_s[WARPS], sm_sc[WARPS];
    __shared__ float sm_mg, sm_stot;

#pragma unroll
    for (int q = 0; q < 4; q++) {
        const int d0i = 4 * lane + 128 * q;
        sm_c[wid][d0i + 0] = c[q].x;
        sm_c[wid][d0i + 1] = c[q].y;
        sm_c[wid][d0i + 2] = c[q].z;
        sm_c[wid][d0i + 3] = c[q].w;
    }
    if (lane == 0) { sm_m[wid] = m; sm_s[wid] = s; }
    __syncthreads();

    if (wid == 0) {
        float mw = (lane < WARPS) ? sm_m[lane] : -CUDART_INF_F;
        float mg = mw;
#pragma unroll
        for (int o = 16; o > 0; o >>= 1)
            mg = fmaxf(mg, __shfl_xor_sync(0xffffffffu, mg, o));
        float sc = (lane < WARPS) ? __expf(mw - mg) : 0.f;
        float st = (lane < WARPS) ? sm_s[lane] * sc : 0.f;
#pragma unroll
        for (int o = 16; o > 0; o >>= 1)
            st += __shfl_xor_sync(0xffffffffu, st, o);
        if (lane < WARPS) sm_sc[lane] = sc;
        if (lane == 0) { sm_mg = mg; sm_stot = st; }
    }
    __syncthreads();

    float* out = g_scratch + ((size_t)b * NS + split) * (DD + 2);
    for (int d = tid; d < DD; d += NTHREADS) {
        float acc = 0.f;
#pragma unroll
        for (int w = 0; w < WARPS; w++)
            acc = fmaf(sm_c[w][d], sm_sc[w], acc);
        out[d] = acc;
    }
    if (tid == 0) { out[DD] = sm_mg; out[DD + 1] = sm_stot; }
}

// 512 blocks x 64 threads: block (b, octant) handles 64 d-values
__global__ void __launch_bounds__(64)
attn_pass2(float* __restrict__ outp) {
    const int b   = blockIdx.x >> 3;
    const int oct = blockIdx.x & 7;
    const int tid = threadIdx.x;

    __shared__ float sm_sc[NS];
    __shared__ float sm_stot;

    const float* base = g_scratch + (size_t)b * NS * (DD + 2);

    if (tid < 32) {
        float mw = (tid < NS) ? base[(size_t)tid * (DD + 2) + DD] : -CUDART_INF_F;
        float mg = mw;
#pragma unroll
        for (int o = 16; o > 0; o >>= 1)
            mg = fmaxf(mg, __shfl_xor_sync(0xffffffffu, mg, o));
        float sc = (tid < NS) ? __expf(mw - mg) : 0.f;
        float st = (tid < NS) ? base[(size_t)tid * (DD + 2) + DD + 1] * sc : 0.f;
#pragma unroll
        for (int o = 16; o > 0; o >>= 1)
            st += __shfl_xor_sync(0xffffffffu, st, o);
        if (tid < NS) sm_sc[tid] = sc;
        if (tid == 0) sm_stot = st;
    }
    __syncthreads();

    const float inv = 1.f / (sm_stot * (float)LL);
    const int d = oct * 64 + tid;
    float acc = 0.f;
#pragma unroll
    for (int w = 0; w < NS; w++)
        acc = fmaf(base[(size_t)w * (DD + 2) + d], sm_sc[w], acc);
    outp[(size_t)b * DD + d] = acc * inv;
}

extern "C" void kernel_launch(void* const* d_in, const int* in_sizes, int n_in,
                              void* d_out, int out_size) {
    const float* h = (const float*)d_in[0];   // current_hidden [64, 512]
    const float* E = (const float*)d_in[1];   // encoder_outputs [64, 4096, 512]
    float* outp = (float*)d_out;              // [64, 512]

    attn_pass1<<<BB * NS, NTHREADS>>>(h, E);
    attn_pass2<<<BB * 8, 64>>>(outp);
}